// round 15
// baseline (speedup 1.0000x reference)
#include <cuda_runtime.h>
#include <cuda_bf16.h>
#include <math.h>

#define NSPIN 256
#define FDIM  64
#define BATCH 64
#define NITER 40
#define TOLF  1e-4f
#define NBLK2 136u

// bf16 tile planes, row stride 264 bf16 = 528 bytes (conflict-free ldmatrix)
#define ROWB 528
#define AHI  0
#define ALO  67584            // 128*528
#define BHI  135168           // 2*128*528
#define BLO  168960           // +64*528
#define SMEM_SZ 202752

// -------------------- device scratch --------------------
__device__ unsigned g_Jp [NSPIN * NSPIN];        // J packed (bf16 hi | lo<<16)
__device__ unsigned g_HT [BATCH * FDIM * NSPIN]; // h^T packed [b][n][k]
__device__ unsigned g_U1p[BATCH * FDIM * NSPIN]; // u1^T packed [b][n][k]
__device__ float g_rowsq[NSPIN];                 // per-row sum J^2 (fp32 exact)
__device__ float g_mAA0[BATCH][2], g_mAC0[BATCH][2], g_mAA1[BATCH][2];
__device__ float g_mAC1[BATCH][2], g_mCC[BATCH][2];
__device__ float g_tAC[2][4], g_tCC[2][4];
__device__ unsigned g_bar;                       // monotonic ticket

#define VL(x) (*(volatile float*)&(x))

// -------------------- helpers --------------------
__device__ __forceinline__ unsigned smem_u32(const void* p) {
    unsigned a;
    asm("{ .reg .u64 t; cvta.to.shared.u64 t, %1; cvt.u32.u64 %0, t; }" : "=r"(a) : "l"(p));
    return a;
}
__device__ __forceinline__ void ldm_x4(unsigned r[4], unsigned addr) {
    asm volatile("ldmatrix.sync.aligned.m8n8.x4.shared.b16 {%0,%1,%2,%3}, [%4];"
        : "=r"(r[0]), "=r"(r[1]), "=r"(r[2]), "=r"(r[3]) : "r"(addr));
}
__device__ __forceinline__ void mma_bf16(float d[4], const unsigned a[4], const unsigned b[2]) {
    asm volatile("mma.sync.aligned.m16n8k16.row.col.f32.bf16.bf16.f32 "
        "{%0,%1,%2,%3}, {%4,%5,%6,%7}, {%8,%9}, {%0,%1,%2,%3};"
        : "+f"(d[0]), "+f"(d[1]), "+f"(d[2]), "+f"(d[3])
        : "r"(a[0]), "r"(a[1]), "r"(a[2]), "r"(a[3]), "r"(b[0]), "r"(b[1]));
}
__device__ __forceinline__ unsigned packf(float v) {
    __nv_bfloat16 h = __float2bfloat16(v);
    __nv_bfloat16 l = __float2bfloat16(v - __bfloat162float(h));
    return (unsigned)__bfloat16_as_ushort(h) | ((unsigned)__bfloat16_as_ushort(l) << 16);
}
__device__ __forceinline__ float unpackf(unsigned e) {
    return __bfloat162float(__ushort_as_bfloat16((unsigned short)(e & 0xFFFF)))
         + __bfloat162float(__ushort_as_bfloat16((unsigned short)(e >> 16)));
}

// stage packed u32 rows (256 k per row) into hi/lo bf16 planes, row stride 528 B
template <int R>
__device__ __forceinline__ void stage_planes(char* sm, int hi_off, int lo_off,
                                             const unsigned* src, int tid) {
    for (int idx = tid; idx < R * 128; idx += 512) {
        int r = idx >> 7, kp = idx & 127;
        unsigned e0 = src[r * 256 + 2 * kp], e1 = src[r * 256 + 2 * kp + 1];
        unsigned hp = (e0 & 0xFFFFu) | (e1 << 16);
        unsigned lp = (e0 >> 16) | (e1 & 0xFFFF0000u);
        int off = r * ROWB + kp * 4;
        *(unsigned*)(sm + hi_off + off) = hp;
        *(unsigned*)(sm + lo_off + off) = lp;
    }
}

__device__ __forceinline__ float blockReduceSum(float v, float* sc) {
    #pragma unroll
    for (int o = 16; o > 0; o >>= 1) v += __shfl_down_sync(0xffffffffu, v, o);
    int lane = threadIdx.x & 31, w = threadIdx.x >> 5;
    if (lane == 0) sc[w] = v;
    __syncthreads();
    float r = 0.f;
    if (w == 0) {
        r = (lane < 16) ? sc[lane] : 0.f;
        #pragma unroll
        for (int o = 8; o > 0; o >>= 1) r += __shfl_down_sync(0xffffffffu, r, o);
    }
    __syncthreads();
    return r;
}

// full 3-plane split gemm: d[mt][nt][4] accumulators (dual sets to break dep chains)
__device__ __forceinline__ void gemm_split(unsigned sb, unsigned aoff0, unsigned aoff1,
                                           unsigned boff, float d[2][2][4]) {
    float e[2][2][4];
    #pragma unroll
    for (int i = 0; i < 2; i++)
        #pragma unroll
        for (int j = 0; j < 2; j++)
            #pragma unroll
            for (int q = 0; q < 4; q++) { d[i][j][q] = 0.f; e[i][j][q] = 0.f; }
    #pragma unroll
    for (int pl = 0; pl < 3; pl++) {
        unsigned pa = sb + (pl == 2 ? ALO : AHI);
        unsigned pb = sb + (pl == 1 ? BLO : BHI);
        #pragma unroll
        for (int kk = 0; kk < 512; kk += 64) {   // kk in bytes (k*2); 2 k-steps/iter
            unsigned a0[4], a1[4], bb[4];
            ldm_x4(a0, pa + aoff0 + kk); ldm_x4(a1, pa + aoff1 + kk);
            ldm_x4(bb, pb + boff + kk);
            mma_bf16(d[0][0], a0, bb); mma_bf16(d[0][1], a0, bb + 2);
            mma_bf16(d[1][0], a1, bb); mma_bf16(d[1][1], a1, bb + 2);
            ldm_x4(a0, pa + aoff0 + kk + 32); ldm_x4(a1, pa + aoff1 + kk + 32);
            ldm_x4(bb, pb + boff + kk + 32);
            mma_bf16(e[0][0], a0, bb); mma_bf16(e[0][1], a0, bb + 2);
            mma_bf16(e[1][0], a1, bb); mma_bf16(e[1][1], a1, bb + 2);
        }
    }
    #pragma unroll
    for (int i = 0; i < 2; i++)
        #pragma unroll
        for (int j = 0; j < 2; j++)
            #pragma unroll
            for (int q = 0; q < 4; q++) d[i][j][q] += e[i][j][q];
}

// -------------------- kernel 1: prep (grid 256, 256 thr) -----------------------
__global__ void prep(const float* __restrict__ x, const float* __restrict__ Jr) {
    __shared__ float ts[64][65];
    __shared__ float sc[8];
    const int bid = blockIdx.x, tid = threadIdx.x;
    {
        int r = bid, j = tid;
        float v = (r == j) ? 0.f : 0.5f * (Jr[r * NSPIN + j] + Jr[j * NSPIN + r]);
        g_Jp[r * NSPIN + j] = packf(v);
        float s = v * v;
        #pragma unroll
        for (int o = 16; o > 0; o >>= 1) s += __shfl_down_sync(0xffffffffu, s, o);
        if ((tid & 31) == 0) sc[tid >> 5] = s;
        __syncthreads();
        if (tid == 0) {
            float t = 0.f;
            #pragma unroll
            for (int q = 0; q < 8; q++) t += sc[q];
            g_rowsq[r] = t;
        }
    }
    const int b = bid >> 2, k0 = (bid & 3) * 64;
    for (int idx = tid; idx < 4096; idx += 256) {
        int kk = idx >> 6, n = idx & 63;
        ts[n][kk] = x[((size_t)b * NSPIN + k0 + kk) * FDIM + n];
    }
    __syncthreads();
    for (int idx = tid; idx < 4096; idx += 256) {
        int n = idx >> 6, kk = idx & 63;
        g_HT[((size_t)b * FDIM + n) * NSPIN + k0 + kk] = packf(ts[n][kk]);
    }
}

// -------------------- kernel 2: p1 (grid 128, 512 thr): u1 = J h ---------------
__global__ void __launch_bounds__(512, 1)
p1(const float* __restrict__ x) {
    extern __shared__ char sm[];
    __shared__ float sc[16];
    const int bid = blockIdx.x, tid = threadIdx.x;
    const int b = bid >> 1, rt = bid & 1, row0 = rt * 128;
    const unsigned sb = smem_u32(sm);

    stage_planes<128>(sm, AHI, ALO, g_Jp + row0 * NSPIN, tid);
    stage_planes<64>(sm, BHI, BLO, g_HT + (size_t)b * FDIM * NSPIN, tid);
    __syncthreads();

    const int lane = tid & 31, wid = tid >> 5;
    const int wm = wid >> 2, wn = wid & 3;
    const int mbase = wm * 32, nbase = wn * 16;
    const int tt = lane >> 3, rr = lane & 7;
    const unsigned aoff0 = (mbase + (tt & 1) * 8 + rr) * ROWB + (tt >> 1) * 16;
    const unsigned aoff1 = aoff0 + 16 * ROWB;
    const unsigned boff  = (nbase + (tt >> 1) * 8 + rr) * ROWB + (tt & 1) * 16;

    float d[2][2][4];
    gemm_split(sb, aoff0, aoff1, boff, d);

    // epilogue: m0=||h||^2, m1=<h,u1>, m2=||u1||^2 (own half); write u1^T packed
    const int qr = lane >> 2, qc = (lane & 3) * 2;
    float m0 = 0.f, m1 = 0.f, m2 = 0.f;
    unsigned* up = g_U1p + (size_t)b * FDIM * NSPIN;
    const float* xb = x + (size_t)b * NSPIN * FDIM;
    #pragma unroll
    for (int mt = 0; mt < 2; mt++)
        #pragma unroll
        for (int nt = 0; nt < 2; nt++)
            #pragma unroll
            for (int hh = 0; hh < 2; hh++) {
                int m = row0 + mbase + mt * 16 + qr + hh * 8;
                int gn = nbase + nt * 8 + qc;
                float d0 = d[mt][nt][hh * 2], d1 = d[mt][nt][hh * 2 + 1];
                m2 += d0 * d0 + d1 * d1;
                float2 hv = *(const float2*)&xb[(size_t)m * FDIM + gn];
                m0 += hv.x * hv.x + hv.y * hv.y;
                m1 += hv.x * d0 + hv.y * d1;
                up[(size_t)gn * NSPIN + m] = packf(d0);
                up[(size_t)(gn + 1) * NSPIN + m] = packf(d1);
            }
    float red;
    red = blockReduceSum(m0, sc); if (tid == 0) g_mAA0[b][rt] = red;
    red = blockReduceSum(m1, sc); if (tid == 0) g_mAC0[b][rt] = red;
    red = blockReduceSum(m2, sc); if (tid == 0) g_mAA1[b][rt] = red;
}

// -------------------- newton tail --------------------
__device__ void newton_tail(int b, float tp2, float* out, int out_size) {
    float m0 = VL(g_mAA0[b][0]) + VL(g_mAA0[b][1]);
    float m1 = VL(g_mAC0[b][0]) + VL(g_mAC0[b][1]);
    float m2 = VL(g_mAA1[b][0]) + VL(g_mAA1[b][1]);
    float m3 = VL(g_mAC1[b][0]) + VL(g_mAC1[b][1]);
    float m4 = VL(g_mCC [b][0]) + VL(g_mCC [b][1]);

    float tp3 = 0.f, tp4 = 0.f;
    #pragma unroll
    for (int r = 0; r < 2; r++)
        #pragma unroll
        for (int q = 0; q < 4; q++) { tp3 += VL(g_tAC[r][q]); tp4 += VL(g_tCC[r][q]); }

    const float cSb2 = 3.f * tp2, cSb3 = 4.f * tp3, cSb4 = 5.f * tp4;
    const float cQb0 = m0, cQb1 = 2.f*m1, cQb2 = 3.f*m2, cQb3 = 4.f*m3, cQb4 = 5.f*m4;
    const float cQc0 = m0, cQc1 = 3.f*m1, cQc2 = 6.f*m2, cQc3 = 10.f*m3, cQc4 = 15.f*m4;

    float t = 1.0f;
    for (int it = 0; it < NITER; ++it) {
        float xv = 1.0f / t;
        float Sa = (((tp4 * xv + tp3) * xv + tp2) * xv) * xv + 256.f;
        float Sb = (((cSb4 * xv + cSb3) * xv + cSb2) * xv) * xv + 256.f;
        float Qb = (((cQb4 * xv + cQb3) * xv + cQb2) * xv + cQb1) * xv + cQb0;
        float Qc = (((cQc4 * xv + cQc3) * xv + cQc2) * xv + cQc1) * xv + cQc0;
        float g  = 256.f - 0.5f * (xv * Sa) - (xv * xv * Qb) * (1.f / 256.f);
        if (fabsf(g) <= TOLF) break;       // reference's update is 0 from here on
        float gp = 0.5f * (xv * xv * Sb) + (xv * xv * xv * Qc) * (1.f / 128.f);
        t -= g / gp;
    }
    float xv = 1.0f / t;
    float q1 = xv * ((((m4 * xv + m3) * xv + m2) * xv + m1) * xv + m0);
    float lds = ((tp4 * 0.25f * xv + tp3 * (1.f / 3.f)) * xv + tp2 * 0.5f) * xv * xv;
    float logdet = 256.f * __logf(t) - lds;
    float phi = 256.f * t - 0.5f * logdet + q1 * (1.f / 256.f);
    out[b] = -(0.57236494292f + phi * (1.f / 256.f));
    if (out_size >= 2 * BATCH) out[BATCH + b] = t;
}

// -------------------- kernel 3: p2 (grid 136, 512 thr) -------------------------
__global__ void __launch_bounds__(512, 1)
p2(float* __restrict__ out, int out_size) {
    extern __shared__ char sm[];
    __shared__ float sc[16];
    __shared__ unsigned islast;
    __shared__ float s_tp2;
    const int bid = blockIdx.x, tid = threadIdx.x;
    const bool isH = (bid < 128);
    int b = 0, rt, ct = 0;
    if (isH) { b = bid >> 1; rt = bid & 1; }
    else     { int tb = bid - 128; rt = tb >> 2; ct = tb & 3; }
    const int row0 = rt * 128, col0 = ct * 64;
    const unsigned sb = smem_u32(sm);

    stage_planes<128>(sm, AHI, ALO, g_Jp + row0 * NSPIN, tid);
    if (isH) stage_planes<64>(sm, BHI, BLO, g_U1p + (size_t)b * FDIM * NSPIN, tid);
    else     stage_planes<64>(sm, BHI, BLO, g_Jp + col0 * NSPIN, tid);
    __syncthreads();

    const int lane = tid & 31, wid = tid >> 5;
    const int wm = wid >> 2, wn = wid & 3;
    const int mbase = wm * 32, nbase = wn * 16;
    const int tt = lane >> 3, rr = lane & 7;
    const unsigned aoff0 = (mbase + (tt & 1) * 8 + rr) * ROWB + (tt >> 1) * 16;
    const unsigned aoff1 = aoff0 + 16 * ROWB;
    const unsigned boff  = (nbase + (tt >> 1) * 8 + rr) * ROWB + (tt & 1) * 16;

    float d[2][2][4];
    gemm_split(sb, aoff0, aoff1, boff, d);

    const int qr = lane >> 2, qc = (lane & 3) * 2;
    float ac = 0.f, cc = 0.f;
    if (isH) {
        const unsigned* up = g_U1p + (size_t)b * FDIM * NSPIN;
        #pragma unroll
        for (int mt = 0; mt < 2; mt++)
            #pragma unroll
            for (int nt = 0; nt < 2; nt++)
                #pragma unroll
                for (int hh = 0; hh < 2; hh++) {
                    int m = row0 + mbase + mt * 16 + qr + hh * 8;
                    int gn = nbase + nt * 8 + qc;
                    float d0 = d[mt][nt][hh * 2], d1 = d[mt][nt][hh * 2 + 1];
                    cc += d0 * d0 + d1 * d1;
                    ac += d0 * unpackf(up[(size_t)gn * NSPIN + m])
                        + d1 * unpackf(up[(size_t)(gn + 1) * NSPIN + m]);
                }
    } else {
        #pragma unroll
        for (int mt = 0; mt < 2; mt++)
            #pragma unroll
            for (int nt = 0; nt < 2; nt++)
                #pragma unroll
                for (int hh = 0; hh < 2; hh++) {
                    int m = row0 + mbase + mt * 16 + qr + hh * 8;
                    int gn = col0 + nbase + nt * 8 + qc;
                    float d0 = d[mt][nt][hh * 2], d1 = d[mt][nt][hh * 2 + 1];
                    cc += d0 * d0 + d1 * d1;
                    ac += d0 * unpackf(g_Jp[(size_t)m * NSPIN + gn])
                        + d1 * unpackf(g_Jp[(size_t)m * NSPIN + gn + 1]);
                }
    }
    float red;
    red = blockReduceSum(ac, sc);
    if (tid == 0) { if (isH) g_mAC1[b][rt] = red; else g_tAC[rt][ct] = red; }
    red = blockReduceSum(cc, sc);
    if (tid == 0) { if (isH) g_mCC[b][rt] = red; else g_tCC[rt][ct] = red; }

    if (tid == 0) {
        islast = 0u;
        __threadfence();
        unsigned old = atomicAdd(&g_bar, 1u);
        if ((old % NBLK2) == NBLK2 - 1u) islast = 1u;
    }
    __syncthreads();
    if (islast) {
        __threadfence();
        if (tid < 32) {
            float s = 0.f;
            for (int q = tid; q < NSPIN; q += 32) s += VL(g_rowsq[q]);
            #pragma unroll
            for (int o = 16; o > 0; o >>= 1) s += __shfl_down_sync(0xffffffffu, s, o);
            if (tid == 0) s_tp2 = s;
        }
        __syncthreads();
        if (tid < BATCH) newton_tail(tid, s_tp2, out, out_size);
    }
}

// -------------------- launch --------------------
extern "C" void kernel_launch(void* const* d_in, const int* in_sizes, int n_in,
                              void* d_out, int out_size) {
    const float* x  = (const float*)d_in[0];   // (64, 256, 64)
    const float* Jr = (const float*)d_in[1];   // (256, 256)
    float* out = (float*)d_out;

    cudaFuncSetAttribute(p1, cudaFuncAttributeMaxDynamicSharedMemorySize, SMEM_SZ);
    cudaFuncSetAttribute(p2, cudaFuncAttributeMaxDynamicSharedMemorySize, SMEM_SZ);

    prep<<<256, 256>>>(x, Jr);
    p1<<<128, 512, SMEM_SZ>>>(x);
    p2<<<136, 512, SMEM_SZ>>>(out, out_size);
}

// round 17
// speedup vs baseline: 1.0900x; 1.0900x over previous
#include <cuda_runtime.h>
#include <cuda_bf16.h>
#include <math.h>

#define NSPIN 256
#define FDIM  64
#define BATCH 64
#define NITER 40
#define TOLF  1e-4f
#define NBLK2 136u

// A planes: [m 128][k 256] bf16, row stride 528 B (conflict-free non-trans ldmatrix)
// B planes: [k 256][n 64]  bf16, row stride 144 B (9 chunks -> conflict-free trans ldmatrix)
//           (matrix path reuses region as [n 64][k 256] stride 528)
#define ROWB 528
#define BROW 144
#define AHI  0
#define ALO  67584            // 128*528
#define BHI  135168
#define BLO  172032           // BHI + 256*144
#define SMEM_SZ 208896

// -------------------- device scratch --------------------
__device__ unsigned g_Jp [NSPIN * NSPIN];        // J packed (bf16 hi | lo<<16), [m][k]
__device__ unsigned g_U1p[BATCH * NSPIN * FDIM]; // u1 packed, [b][k][n]
__device__ float g_rowsq[NSPIN];                 // per-row sum J^2 (fp32 exact)
__device__ float g_mAA0[BATCH][2], g_mAC0[BATCH][2], g_mAA1[BATCH][2];
__device__ float g_mAC1[BATCH][2], g_mCC[BATCH][2];
__device__ float g_tAC[2][4], g_tCC[2][4];
__device__ unsigned g_bar;                       // monotonic ticket

#define VL(x) (*(volatile float*)&(x))

// -------------------- helpers --------------------
__device__ __forceinline__ unsigned smem_u32(const void* p) {
    unsigned a;
    asm("{ .reg .u64 t; cvta.to.shared.u64 t, %1; cvt.u32.u64 %0, t; }" : "=r"(a) : "l"(p));
    return a;
}
__device__ __forceinline__ void ldm_x4(unsigned r[4], unsigned addr) {
    asm volatile("ldmatrix.sync.aligned.m8n8.x4.shared.b16 {%0,%1,%2,%3}, [%4];"
        : "=r"(r[0]), "=r"(r[1]), "=r"(r[2]), "=r"(r[3]) : "r"(addr));
}
__device__ __forceinline__ void ldm_x4t(unsigned r[4], unsigned addr) {
    asm volatile("ldmatrix.sync.aligned.m8n8.x4.trans.shared.b16 {%0,%1,%2,%3}, [%4];"
        : "=r"(r[0]), "=r"(r[1]), "=r"(r[2]), "=r"(r[3]) : "r"(addr));
}
__device__ __forceinline__ void mma_bf16(float d[4], const unsigned a[4], const unsigned b[2]) {
    asm volatile("mma.sync.aligned.m16n8k16.row.col.f32.bf16.bf16.f32 "
        "{%0,%1,%2,%3}, {%4,%5,%6,%7}, {%8,%9}, {%0,%1,%2,%3};"
        : "+f"(d[0]), "+f"(d[1]), "+f"(d[2]), "+f"(d[3])
        : "r"(a[0]), "r"(a[1]), "r"(a[2]), "r"(a[3]), "r"(b[0]), "r"(b[1]));
}
__device__ __forceinline__ unsigned packf(float v) {
    __nv_bfloat16 h = __float2bfloat16(v);
    __nv_bfloat16 l = __float2bfloat16(v - __bfloat162float(h));
    return (unsigned)__bfloat16_as_ushort(h) | ((unsigned)__bfloat16_as_ushort(l) << 16);
}
__device__ __forceinline__ float unpackf(unsigned e) {
    return __bfloat162float(__ushort_as_bfloat16((unsigned short)(e & 0xFFFF)))
         + __bfloat162float(__ushort_as_bfloat16((unsigned short)(e >> 16)));
}

// stage packed u32 rows (256 k per row) into hi/lo [r][k] planes, row stride 528 B
template <int R>
__device__ __forceinline__ void stage_planes(char* sm, int hi_off, int lo_off,
                                             const unsigned* src, int tid) {
    for (int idx = tid; idx < R * 128; idx += 512) {
        int r = idx >> 7, kp = idx & 127;
        unsigned e0 = src[r * 256 + 2 * kp], e1 = src[r * 256 + 2 * kp + 1];
        unsigned hp = (e0 & 0xFFFFu) | (e1 << 16);
        unsigned lp = (e0 >> 16) | (e1 & 0xFFFF0000u);
        int off = r * ROWB + kp * 4;
        *(unsigned*)(sm + hi_off + off) = hp;
        *(unsigned*)(sm + lo_off + off) = lp;
    }
}

// stage fp32 [k 256][n 64] source into hi/lo [k][n] planes, row stride 144 B
__device__ __forceinline__ void stage_x_kn(char* sm, const float* src, int tid) {
    for (int idx = tid; idx < 256 * 32; idx += 512) {
        int k = idx >> 5, np = idx & 31, n = np * 2;
        float2 v = *(const float2*)&src[(size_t)k * FDIM + n];
        unsigned p0 = packf(v.x), p1 = packf(v.y);
        unsigned hp = (p0 & 0xFFFFu) | (p1 << 16);
        unsigned lp = (p0 >> 16) | (p1 & 0xFFFF0000u);
        int off = k * BROW + n * 2;
        *(unsigned*)(sm + BHI + off) = hp;
        *(unsigned*)(sm + BLO + off) = lp;
    }
}

// stage packed u32 [k 256][n 64] source into hi/lo [k][n] planes, row stride 144 B
__device__ __forceinline__ void stage_u1_kn(char* sm, const unsigned* src, int tid) {
    for (int idx = tid; idx < 256 * 32; idx += 512) {
        int k = idx >> 5, np = idx & 31, n = np * 2;
        unsigned e0 = src[(size_t)k * FDIM + n], e1 = src[(size_t)k * FDIM + n + 1];
        unsigned hp = (e0 & 0xFFFFu) | (e1 << 16);
        unsigned lp = (e0 >> 16) | (e1 & 0xFFFF0000u);
        int off = k * BROW + n * 2;
        *(unsigned*)(sm + BHI + off) = hp;
        *(unsigned*)(sm + BLO + off) = lp;
    }
}

__device__ __forceinline__ float blockReduceSum(float v, float* sc) {
    #pragma unroll
    for (int o = 16; o > 0; o >>= 1) v += __shfl_down_sync(0xffffffffu, v, o);
    int lane = threadIdx.x & 31, w = threadIdx.x >> 5;
    if (lane == 0) sc[w] = v;
    __syncthreads();
    float r = 0.f;
    if (w == 0) {
        r = (lane < 16) ? sc[lane] : 0.f;
        #pragma unroll
        for (int o = 8; o > 0; o >>= 1) r += __shfl_down_sync(0xffffffffu, r, o);
    }
    __syncthreads();
    return r;
}

// 3-plane split gemm; BT=1: B stored [k][n] stride BROW (trans ldmatrix),
//                     BT=0: B stored [n][k] stride ROWB (non-trans).
template <int BT>
__device__ __forceinline__ void gemm_split(unsigned sb, unsigned aoff0, unsigned aoff1,
                                           unsigned boff, float d[2][2][4]) {
    float e[2][2][4];
    #pragma unroll
    for (int i = 0; i < 2; i++)
        #pragma unroll
        for (int j = 0; j < 2; j++)
            #pragma unroll
            for (int q = 0; q < 4; q++) { d[i][j][q] = 0.f; e[i][j][q] = 0.f; }
    #pragma unroll
    for (int pl = 0; pl < 3; pl++) {
        unsigned pa = sb + (pl == 2 ? ALO : AHI);
        unsigned pb = sb + (pl == 1 ? BLO : BHI);
        #pragma unroll
        for (int ks = 0; ks < 16; ks += 2) {     // 16-k steps
            unsigned a0[4], a1[4], bb[4];
            ldm_x4(a0, pa + aoff0 + ks * 32);
            ldm_x4(a1, pa + aoff1 + ks * 32);
            if (BT) ldm_x4t(bb, pb + boff + ks * (16 * BROW));
            else    ldm_x4 (bb, pb + boff + ks * 32);
            mma_bf16(d[0][0], a0, bb); mma_bf16(d[0][1], a0, bb + 2);
            mma_bf16(d[1][0], a1, bb); mma_bf16(d[1][1], a1, bb + 2);
            ldm_x4(a0, pa + aoff0 + ks * 32 + 32);
            ldm_x4(a1, pa + aoff1 + ks * 32 + 32);
            if (BT) ldm_x4t(bb, pb + boff + ks * (16 * BROW) + 16 * BROW);
            else    ldm_x4 (bb, pb + boff + ks * 32 + 32);
            mma_bf16(e[0][0], a0, bb); mma_bf16(e[0][1], a0, bb + 2);
            mma_bf16(e[1][0], a1, bb); mma_bf16(e[1][1], a1, bb + 2);
        }
    }
    #pragma unroll
    for (int i = 0; i < 2; i++)
        #pragma unroll
        for (int j = 0; j < 2; j++)
            #pragma unroll
            for (int q = 0; q < 4; q++) d[i][j][q] += e[i][j][q];
}

// -------------------- kernel 1: prep (grid 256, 256 thr): build J only --------
__global__ void prep(const float* __restrict__ Jr) {
    __shared__ float sc[8];
    const int r = blockIdx.x, j = threadIdx.x, tid = threadIdx.x;
    float v = (r == j) ? 0.f : 0.5f * (Jr[r * NSPIN + j] + Jr[j * NSPIN + r]);
    g_Jp[r * NSPIN + j] = packf(v);
    float s = v * v;
    #pragma unroll
    for (int o = 16; o > 0; o >>= 1) s += __shfl_down_sync(0xffffffffu, s, o);
    if ((tid & 31) == 0) sc[tid >> 5] = s;
    __syncthreads();
    if (tid == 0) {
        float t = 0.f;
        #pragma unroll
        for (int q = 0; q < 8; q++) t += sc[q];
        g_rowsq[r] = t;
    }
}

// -------------------- kernel 2: p1 (grid 128, 512 thr): u1 = J h ---------------
__global__ void __launch_bounds__(512, 1)
p1(const float* __restrict__ x) {
    extern __shared__ char sm[];
    __shared__ float sc[16];
    const int bid = blockIdx.x, tid = threadIdx.x;
    const int b = bid >> 1, rt = bid & 1, row0 = rt * 128;
    const unsigned sb = smem_u32(sm);

    stage_planes<128>(sm, AHI, ALO, g_Jp + row0 * NSPIN, tid);
    stage_x_kn(sm, x + (size_t)b * NSPIN * FDIM, tid);
    __syncthreads();

    const int lane = tid & 31, wid = tid >> 5;
    const int wm = wid >> 2, wn = wid & 3;
    const int mbase = wm * 32, nbase = wn * 16;
    const int tt = lane >> 3, rr = lane & 7;
    const unsigned aoff0 = (mbase + (tt & 1) * 8 + rr) * ROWB + (tt >> 1) * 16;
    const unsigned aoff1 = aoff0 + 16 * ROWB;
    const unsigned bofft = ((tt & 1) * 8 + rr) * BROW + (nbase + (tt >> 1) * 8) * 2;

    float d[2][2][4];
    gemm_split<1>(sb, aoff0, aoff1, bofft, d);

    // epilogue: m0=||h||^2, m1=<h,u1>, m2=||u1||^2 (own half); u1 -> [k][n] packed
    const int qr = lane >> 2, qc = (lane & 3) * 2;
    float m0 = 0.f, m1 = 0.f, m2 = 0.f;
    unsigned* up = g_U1p + (size_t)b * NSPIN * FDIM;
    const float* xb = x + (size_t)b * NSPIN * FDIM;
    #pragma unroll
    for (int mt = 0; mt < 2; mt++)
        #pragma unroll
        for (int nt = 0; nt < 2; nt++)
            #pragma unroll
            for (int hh = 0; hh < 2; hh++) {
                int m = row0 + mbase + mt * 16 + qr + hh * 8;
                int gn = nbase + nt * 8 + qc;
                float d0 = d[mt][nt][hh * 2], d1 = d[mt][nt][hh * 2 + 1];
                m2 += d0 * d0 + d1 * d1;
                float2 hv = *(const float2*)&xb[(size_t)m * FDIM + gn];
                m0 += hv.x * hv.x + hv.y * hv.y;
                m1 += hv.x * d0 + hv.y * d1;
                uint2 w = make_uint2(packf(d0), packf(d1));
                *(uint2*)&up[(size_t)m * FDIM + gn] = w;
            }
    float red;
    red = blockReduceSum(m0, sc); if (tid == 0) g_mAA0[b][rt] = red;
    red = blockReduceSum(m1, sc); if (tid == 0) g_mAC0[b][rt] = red;
    red = blockReduceSum(m2, sc); if (tid == 0) g_mAA1[b][rt] = red;
}

// -------------------- newton tail --------------------
__device__ void newton_tail(int b, float tp2, float* out, int out_size) {
    float m0 = VL(g_mAA0[b][0]) + VL(g_mAA0[b][1]);
    float m1 = VL(g_mAC0[b][0]) + VL(g_mAC0[b][1]);
    float m2 = VL(g_mAA1[b][0]) + VL(g_mAA1[b][1]);
    float m3 = VL(g_mAC1[b][0]) + VL(g_mAC1[b][1]);
    float m4 = VL(g_mCC [b][0]) + VL(g_mCC [b][1]);

    float tp3 = 0.f, tp4 = 0.f;
    #pragma unroll
    for (int r = 0; r < 2; r++)
        #pragma unroll
        for (int q = 0; q < 4; q++) { tp3 += VL(g_tAC[r][q]); tp4 += VL(g_tCC[r][q]); }

    const float cSb2 = 3.f * tp2, cSb3 = 4.f * tp3, cSb4 = 5.f * tp4;
    const float cQb0 = m0, cQb1 = 2.f*m1, cQb2 = 3.f*m2, cQb3 = 4.f*m3, cQb4 = 5.f*m4;
    const float cQc0 = m0, cQc1 = 3.f*m1, cQc2 = 6.f*m2, cQc3 = 10.f*m3, cQc4 = 15.f*m4;

    float t = 1.0f;
    for (int it = 0; it < NITER; ++it) {
        float xv = 1.0f / t;
        float Sa = (((tp4 * xv + tp3) * xv + tp2) * xv) * xv + 256.f;
        float Sb = (((cSb4 * xv + cSb3) * xv + cSb2) * xv) * xv + 256.f;
        float Qb = (((cQb4 * xv + cQb3) * xv + cQb2) * xv + cQb1) * xv + cQb0;
        float Qc = (((cQc4 * xv + cQc3) * xv + cQc2) * xv + cQc1) * xv + cQc0;
        float g  = 256.f - 0.5f * (xv * Sa) - (xv * xv * Qb) * (1.f / 256.f);
        if (fabsf(g) <= TOLF) break;       // reference's update is 0 from here on
        float gp = 0.5f * (xv * xv * Sb) + (xv * xv * xv * Qc) * (1.f / 128.f);
        t -= g / gp;
    }
    float xv = 1.0f / t;
    float q1 = xv * ((((m4 * xv + m3) * xv + m2) * xv + m1) * xv + m0);
    float lds = ((tp4 * 0.25f * xv + tp3 * (1.f / 3.f)) * xv + tp2 * 0.5f) * xv * xv;
    float logdet = 256.f * __logf(t) - lds;
    float phi = 256.f * t - 0.5f * logdet + q1 * (1.f / 256.f);
    out[b] = -(0.57236494292f + phi * (1.f / 256.f));
    if (out_size >= 2 * BATCH) out[BATCH + b] = t;
}

// -------------------- kernel 3: p2 (grid 136, 512 thr) -------------------------
__global__ void __launch_bounds__(512, 1)
p2(float* __restrict__ out, int out_size) {
    extern __shared__ char sm[];
    __shared__ float sc[16];
    __shared__ unsigned islast;
    __shared__ float s_tp2;
    const int bid = blockIdx.x, tid = threadIdx.x;
    const bool isH = (bid < 128);
    int b = 0, rt, ct = 0;
    if (isH) { b = bid >> 1; rt = bid & 1; }
    else     { int tb = bid - 128; rt = tb >> 2; ct = tb & 3; }
    const int row0 = rt * 128, col0 = ct * 64;
    const unsigned sb = smem_u32(sm);

    stage_planes<128>(sm, AHI, ALO, g_Jp + row0 * NSPIN, tid);
    if (isH) stage_u1_kn(sm, g_U1p + (size_t)b * NSPIN * FDIM, tid);
    else     stage_planes<64>(sm, BHI, BLO, g_Jp + col0 * NSPIN, tid);
    __syncthreads();

    const int lane = tid & 31, wid = tid >> 5;
    const int wm = wid >> 2, wn = wid & 3;
    const int mbase = wm * 32, nbase = wn * 16;
    const int tt = lane >> 3, rr = lane & 7;
    const unsigned aoff0 = (mbase + (tt & 1) * 8 + rr) * ROWB + (tt >> 1) * 16;
    const unsigned aoff1 = aoff0 + 16 * ROWB;
    const unsigned bofft = ((tt & 1) * 8 + rr) * BROW + (nbase + (tt >> 1) * 8) * 2;
    const unsigned boffn = (nbase + (tt >> 1) * 8 + rr) * ROWB + (tt & 1) * 16;

    float d[2][2][4];
    if (isH) gemm_split<1>(sb, aoff0, aoff1, bofft, d);
    else     gemm_split<0>(sb, aoff0, aoff1, boffn, d);

    const int qr = lane >> 2, qc = (lane & 3) * 2;
    float ac = 0.f, cc = 0.f;
    if (isH) {
        const unsigned* up = g_U1p + (size_t)b * NSPIN * FDIM;
        #pragma unroll
        for (int mt = 0; mt < 2; mt++)
            #pragma unroll
            for (int nt = 0; nt < 2; nt++)
                #pragma unroll
                for (int hh = 0; hh < 2; hh++) {
                    int m = row0 + mbase + mt * 16 + qr + hh * 8;
                    int gn = nbase + nt * 8 + qc;
                    float d0 = d[mt][nt][hh * 2], d1 = d[mt][nt][hh * 2 + 1];
                    cc += d0 * d0 + d1 * d1;
                    uint2 uv = *(const uint2*)&up[(size_t)m * FDIM + gn];
                    ac += d0 * unpackf(uv.x) + d1 * unpackf(uv.y);
                }
    } else {
        #pragma unroll
        for (int mt = 0; mt < 2; mt++)
            #pragma unroll
            for (int nt = 0; nt < 2; nt++)
                #pragma unroll
                for (int hh = 0; hh < 2; hh++) {
                    int m = row0 + mbase + mt * 16 + qr + hh * 8;
                    int gn = col0 + nbase + nt * 8 + qc;
                    float d0 = d[mt][nt][hh * 2], d1 = d[mt][nt][hh * 2 + 1];
                    cc += d0 * d0 + d1 * d1;
                    ac += d0 * unpackf(g_Jp[(size_t)m * NSPIN + gn])
                        + d1 * unpackf(g_Jp[(size_t)m * NSPIN + gn + 1]);
                }
    }
    float red;
    red = blockReduceSum(ac, sc);
    if (tid == 0) { if (isH) g_mAC1[b][rt] = red; else g_tAC[rt][ct] = red; }
    red = blockReduceSum(cc, sc);
    if (tid == 0) { if (isH) g_mCC[b][rt] = red; else g_tCC[rt][ct] = red; }

    if (tid == 0) {
        islast = 0u;
        __threadfence();
        unsigned old = atomicAdd(&g_bar, 1u);
        if ((old % NBLK2) == NBLK2 - 1u) islast = 1u;
    }
    __syncthreads();
    if (islast) {
        __threadfence();
        if (tid < 32) {
            float s = 0.f;
            for (int q = tid; q < NSPIN; q += 32) s += VL(g_rowsq[q]);
            #pragma unroll
            for (int o = 16; o > 0; o >>= 1) s += __shfl_down_sync(0xffffffffu, s, o);
            if (tid == 0) s_tp2 = s;
        }
        __syncthreads();
        if (tid < BATCH) newton_tail(tid, s_tp2, out, out_size);
    }
}

// -------------------- launch --------------------
extern "C" void kernel_launch(void* const* d_in, const int* in_sizes, int n_in,
                              void* d_out, int out_size) {
    const float* x  = (const float*)d_in[0];   // (64, 256, 64)
    const float* Jr = (const float*)d_in[1];   // (256, 256)
    float* out = (float*)d_out;

    cudaFuncSetAttribute(p1, cudaFuncAttributeMaxDynamicSharedMemorySize, SMEM_SZ);
    cudaFuncSetAttribute(p2, cudaFuncAttributeMaxDynamicSharedMemorySize, SMEM_SZ);

    prep<<<256, 256>>>(Jr);
    p1<<<128, 512, SMEM_SZ>>>(x);
    p2<<<136, 512, SMEM_SZ>>>(out, out_size);
}